// round 5
// baseline (speedup 1.0000x reference)
#include <cuda_runtime.h>
#include <float.h>

#define NPTS    8192
#define NB      4
#define NCHUNK  37                 // 4*2*37 = 296 = 148*2 blocks
#define NTILES  2
#define THREADS 256
#define IX      16                 // queries per thread; QTILE = 4096
#define GRID1   (NB * NTILES * NCHUNK)
#define GRID2   256                // reduce: 65536 items / 256

// Scratch (each cell written by exactly one block per run; no init needed).
__device__ float g_rowpart[NCHUNK][NB * NPTS];   // min_m(u) per chunk
__device__ float g_colpart[NTILES][NB * NPTS];   // min_n(d2) per q-tile
__device__ float    g_sum = 0.0f;                // reset by last reduce block
__device__ unsigned g_cnt = 0;

// One pass over each batch's 8192x8192 distance matrix. Block = (b, ntile, chunk).
// Stages ~222 y-points (x,y,z,||y||^2). Each thread owns 16 x-queries.
// Per pair: u = wm - 2 x.y (3 FFMA, row candidate), d2 = u + wn (1 FADD, col
// candidate). Col-min: 4 rotating per-thread partials -> tree -> warp shfl-min.
__global__ __launch_bounds__(THREADS, 2) void chamfer_main(
    const float* __restrict__ x, const float* __restrict__ y)
{
    __shared__ float4 sT[224];
    __shared__ float  sCol[8][224];

    const int bid   = blockIdx.x;
    const int chunk = bid % NCHUNK;
    const int ntile = (bid / NCHUNK) % NTILES;
    const int b     = bid / (NCHUNK * NTILES);

    const float* q = x + (size_t)b * NPTS * 3;
    const float* t = y + (size_t)b * NPTS * 3;

    const int j0  = (NPTS * chunk) / NCHUNK;
    const int j1  = (NPTS * (chunk + 1)) / NCHUNK;
    const int cnt = j1 - j0;                      // 221 or 222

    if (threadIdx.x < cnt) {
        const int j = j0 + threadIdx.x;
        const float tx = t[3 * j + 0];
        const float ty = t[3 * j + 1];
        const float tz = t[3 * j + 2];
        sT[threadIdx.x] = make_float4(tx, ty, tz,
                                      fmaf(tx, tx, fmaf(ty, ty, tz * tz)));
    }
    __syncthreads();

    float ax[IX], ay[IX], az[IX], wn[IX], rm[IX];
    const int qbase = ntile * (THREADS * IX) + threadIdx.x;
#pragma unroll
    for (int i = 0; i < IX; ++i) {
        const int qi = qbase + i * THREADS;
        const float qx = q[3 * qi + 0];
        const float qy = q[3 * qi + 1];
        const float qz = q[3 * qi + 2];
        ax[i] = -2.0f * qx;
        ay[i] = -2.0f * qy;
        az[i] = -2.0f * qz;
        wn[i] = fmaf(qx, qx, fmaf(qy, qy, qz * qz));
        rm[i] = FLT_MAX;
    }

    const int wid  = threadIdx.x >> 5;
    const int lane = threadIdx.x & 31;

    for (int p = 0; p < cnt; ++p) {
        const float4 T = sT[p];                 // warp-broadcast LDS.128
        float c0 = FLT_MAX, c1 = FLT_MAX, c2 = FLT_MAX, c3 = FLT_MAX;
#pragma unroll
        for (int i = 0; i < IX; i += 4) {
            const float u0 = fmaf(ax[i+0], T.x, fmaf(ay[i+0], T.y, fmaf(az[i+0], T.z, T.w)));
            const float u1 = fmaf(ax[i+1], T.x, fmaf(ay[i+1], T.y, fmaf(az[i+1], T.z, T.w)));
            const float u2 = fmaf(ax[i+2], T.x, fmaf(ay[i+2], T.y, fmaf(az[i+2], T.z, T.w)));
            const float u3 = fmaf(ax[i+3], T.x, fmaf(ay[i+3], T.y, fmaf(az[i+3], T.z, T.w)));
            rm[i+0] = fminf(rm[i+0], u0);
            rm[i+1] = fminf(rm[i+1], u1);
            rm[i+2] = fminf(rm[i+2], u2);
            rm[i+3] = fminf(rm[i+3], u3);
            c0 = fminf(c0, u0 + wn[i+0]);
            c1 = fminf(c1, u1 + wn[i+1]);
            c2 = fminf(c2, u2 + wn[i+2]);
            c3 = fminf(c3, u3 + wn[i+3]);
        }
        float tmin = fminf(fminf(c0, c1), fminf(c2, c3));
#pragma unroll
        for (int o = 16; o > 0; o >>= 1)
            tmin = fminf(tmin, __shfl_xor_sync(0xffffffffu, tmin, o));
        if (lane == 0) sCol[wid][p] = tmin;
    }
    __syncthreads();

    const int gq = b * NPTS + qbase;
#pragma unroll
    for (int i = 0; i < IX; ++i)
        g_rowpart[chunk][gq + i * THREADS] = rm[i];

    if (threadIdx.x < cnt) {
        float m = sCol[0][threadIdx.x];
#pragma unroll
        for (int w = 1; w < 8; ++w)
            m = fminf(m, sCol[w][threadIdx.x]);
        g_colpart[ntile][b * NPTS + j0 + threadIdx.x] = m;
    }
}

// 65536 items: [0,32768) row queries (min over 37 chunks, +wn, clamp),
// [32768,65536) col queries (min over 2 tiles, clamp). Last block writes out.
__global__ __launch_bounds__(256) void chamfer_reduce(
    const float* __restrict__ x, float* __restrict__ out)
{
    const int idx = blockIdx.x * 256 + threadIdx.x;

    float v;
    if (idx < NB * NPTS) {
        float m = FLT_MAX;
#pragma unroll
        for (int c = 0; c < NCHUNK; ++c)
            m = fminf(m, g_rowpart[c][idx]);
        const int b = idx >> 13, n = idx & (NPTS - 1);
        const float* q = x + (size_t)b * NPTS * 3;
        const float qx = q[3 * n + 0];
        const float qy = q[3 * n + 1];
        const float qz = q[3 * n + 2];
        v = fmaxf(m + fmaf(qx, qx, fmaf(qy, qy, qz * qz)), 0.0f);
    } else {
        const int j = idx - NB * NPTS;
        float m = g_colpart[0][j];
#pragma unroll
        for (int c = 1; c < NTILES; ++c)
            m = fminf(m, g_colpart[c][j]);
        v = fmaxf(m, 0.0f);
    }

#pragma unroll
    for (int o = 16; o > 0; o >>= 1)
        v += __shfl_xor_sync(0xffffffffu, v, o);

    __shared__ float red[8];
    if ((threadIdx.x & 31) == 0) red[threadIdx.x >> 5] = v;
    __syncthreads();

    if (threadIdx.x < 8) {
        v = red[threadIdx.x];
#pragma unroll
        for (int o = 4; o > 0; o >>= 1)
            v += __shfl_xor_sync(0xffu, v, o);
        if (threadIdx.x == 0) {
            atomicAdd(&g_sum, v);
            __threadfence();
            const unsigned old = atomicAdd(&g_cnt, 1u);
            if (old == GRID2 - 1) {
                const float total = *(volatile float*)&g_sum;
                *out = total * (1.0f / ((float)NPTS * (float)NB));
                g_sum = 0.0f;        // reset for next graph replay
                g_cnt = 0u;
            }
        }
    }
}

extern "C" void kernel_launch(void* const* d_in, const int* in_sizes, int n_in,
                              void* d_out, int out_size)
{
    (void)in_sizes; (void)n_in; (void)out_size;
    const float* x = (const float*)d_in[0];
    const float* y = (const float*)d_in[1];
    float* out = (float*)d_out;

    chamfer_main<<<GRID1, THREADS>>>(x, y);
    chamfer_reduce<<<GRID2, 256>>>(x, out);
}